// round 5
// baseline (speedup 1.0000x reference)
#include <cuda_runtime.h>
#include <cstdint>

// ---------------------------------------------------------------------------
// Fused: h = x @ w^T + b ; instance-norm over OUT ; out = (norm(h)+y)*y
// Single GEMM pass + Gram-identity row stats (see R4).
// R5: 256 threads / 8 warps (4m x 2n, warp tile 32x64). x fragments are held
// in 128 registers per thread (loaded once) -> per-chunk SMEM crossbar
// traffic is b-side only (256KB vs 512KB in R4). w chunks stream via
// double-buffered cp.async.
// ---------------------------------------------------------------------------

#define DEVINL __device__ __forceinline__

static constexpr int IN      = 128;
static constexpr int OUT     = 2048;
static constexpr int MTILE   = 128;
static constexpr int NCHUNK  = 128;
static constexpr int NCHUNKS = OUT / NCHUNK;   // 16
static constexpr int THREADS = 256;            // 8 warps: 4 (m) x 2 (n)
static constexpr int TS      = 132;            // smem tile row stride (floats)

// SMEM layout (floats)
static constexpr int X_OFF    = 0;                  // 128 x 132 (persistent)
static constexpr int W0_OFF   = X_OFF + 128 * TS;   // buf 0
static constexpr int W1_OFF   = W0_OFF + 128 * TS;  // buf 1
static constexpr int MEAN_OFF = W1_OFF + 128 * TS;
static constexpr int DOTC_OFF = MEAN_OFF + 128;
static constexpr int SQ_OFF   = DOTC_OFF + 128;
static constexpr int ISTD_OFF = SQ_OFF + 128;
static constexpr int TOTAL_F  = ISTD_OFF + 128;
static constexpr int SMEM_BYTES = TOTAL_F * 4;      // ~204.8 KB

// ---- device scratch ----
__device__ float g_G[IN * IN];
__device__ float g_c[IN];
__device__ float g_sw[IN];
__device__ float g_db[2];

DEVINL float tf32_trunc(float f) {
    return __uint_as_float(__float_as_uint(f) & 0xFFFFE000u);
}
DEVINL uint32_t f2tf32(float f) {
    uint32_t r;
    asm("cvt.rna.tf32.f32 %0, %1;" : "=r"(r) : "f"(f));
    return r;
}
DEVINL uint32_t smem_u32(const void* p) {
    uint32_t a;
    asm("{ .reg .u64 t; cvta.to.shared.u64 t, %1; cvt.u32.u64 %0, t; }"
        : "=r"(a) : "l"(p));
    return a;
}
DEVINL void cp_async16(uint32_t saddr, const void* g) {
    asm volatile("cp.async.cg.shared.global [%0], [%1], 16;" :: "r"(saddr), "l"(g));
}
#define CP_COMMIT() asm volatile("cp.async.commit_group;" ::: "memory")
#define CP_WAIT(n)  asm volatile("cp.async.wait_group %0;" :: "n"(n) : "memory")

DEVINL void mma_tf32(float* c, uint32_t a0, uint32_t a1, uint32_t a2, uint32_t a3,
                     uint32_t b0, uint32_t b1) {
    asm volatile(
        "mma.sync.aligned.m16n8k8.row.col.f32.tf32.tf32.f32 "
        "{%0,%1,%2,%3}, {%4,%5,%6,%7}, {%8,%9}, {%0,%1,%2,%3};"
        : "+f"(c[0]), "+f"(c[1]), "+f"(c[2]), "+f"(c[3])
        : "r"(a0), "r"(a1), "r"(a2), "r"(a3), "r"(b0), "r"(b1));
}

// ---------------- precompute kernels ----------------

__global__ void zero_scratch_kernel() {
    int i = blockIdx.x * blockDim.x + threadIdx.x;
    if (i < IN * IN) g_G[i] = 0.0f;
    if (i < IN) { g_c[i] = 0.0f; g_sw[i] = 0.0f; }
    if (i < 2)  g_db[i] = 0.0f;
}

__global__ __launch_bounds__(256, 1)
void gram_kernel(const float* __restrict__ w, const float* __restrict__ b) {
    __shared__ float ws[32][IN];
    __shared__ float bs[32];
    const int tid   = threadIdx.x;
    const int jbase = blockIdx.x * 32;

    #pragma unroll
    for (int it = 0; it < 4; ++it) {
        int i  = it * 256 + tid;
        int j  = i >> 5;
        int c4 = (i & 31) * 4;
        float4 v = *reinterpret_cast<const float4*>(w + (size_t)(jbase + j) * IN + c4);
        ws[j][c4 + 0] = tf32_trunc(v.x);
        ws[j][c4 + 1] = tf32_trunc(v.y);
        ws[j][c4 + 2] = tf32_trunc(v.z);
        ws[j][c4 + 3] = tf32_trunc(v.w);
    }
    if (tid < 32) bs[tid] = b[jbase + tid];
    __syncthreads();

    const int k     = tid & 127;
    const int lbase = (tid >> 7) * 64;
    float acc[64];
    #pragma unroll
    for (int l = 0; l < 64; ++l) acc[l] = 0.0f;
    float ck = 0.0f, swk = 0.0f;

    for (int j = 0; j < 32; ++j) {
        float wk = ws[j][k];
        #pragma unroll
        for (int l = 0; l < 64; ++l) acc[l] += wk * ws[j][lbase + l];
        ck  += bs[j] * wk;
        swk += wk;
    }
    #pragma unroll
    for (int l = 0; l < 64; ++l) atomicAdd(&g_G[k * IN + lbase + l], acc[l]);
    if (tid < IN) { atomicAdd(&g_c[k], ck); atomicAdd(&g_sw[k], swk); }
    if (tid < 32) {
        atomicAdd(&g_db[0], bs[tid] * bs[tid]);
        atomicAdd(&g_db[1], bs[tid]);
    }
}

// ---------------- main kernel ----------------

DEVINL void load_x_tile(float* dst, const float* __restrict__ g, int tid) {
    #pragma unroll
    for (int it = 0; it < (128 * 32) / THREADS; ++it) {
        int i  = it * THREADS + tid;
        int r  = i >> 5;
        int c4 = (i & 31) * 4;
        float4 v = *reinterpret_cast<const float4*>(g + (size_t)r * IN + c4);
        float4 o;
        o.x = __uint_as_float(f2tf32(v.x));
        o.y = __uint_as_float(f2tf32(v.y));
        o.z = __uint_as_float(f2tf32(v.z));
        o.w = __uint_as_float(f2tf32(v.w));
        *reinterpret_cast<float4*>(dst + r * TS + c4) = o;
    }
}

DEVINL void issue_w_chunk(uint32_t sbase_f, const float* __restrict__ g, int tid) {
    #pragma unroll
    for (int it = 0; it < (128 * 32) / THREADS; ++it) {
        int i  = it * THREADS + tid;
        int r  = i >> 5;
        int c4 = (i & 31) * 4;
        cp_async16(sbase_f + (uint32_t)(r * TS + c4) * 4u, g + (size_t)r * IN + c4);
    }
}

// b-side-only chunk GEMM: a-fragments come from registers.
DEVINL void compute_chunk_reg(const uint32_t areg[2][16][4],
                              const float* __restrict__ ws,
                              int n0, int g, int tig, float acc[2][8][4]) {
    #pragma unroll
    for (int mt = 0; mt < 2; ++mt)
        #pragma unroll
        for (int nt = 0; nt < 8; ++nt)
            #pragma unroll
            for (int q = 0; q < 4; ++q)
                acc[mt][nt][q] = 0.0f;

    #pragma unroll
    for (int s = 0; s < 16; ++s) {
        uint32_t b[8][2];
        #pragma unroll
        for (int nt = 0; nt < 8; ++nt) {
            const float* wr = ws + (n0 + nt * 8 + g) * TS + s * 8 + tig;
            b[nt][0] = __float_as_uint(wr[0]);
            b[nt][1] = __float_as_uint(wr[4]);
        }
        #pragma unroll
        for (int mt = 0; mt < 2; ++mt)
            #pragma unroll
            for (int nt = 0; nt < 8; ++nt)
                mma_tf32(acc[mt][nt],
                         areg[mt][s][0], areg[mt][s][1], areg[mt][s][2], areg[mt][s][3],
                         b[nt][0], b[nt][1]);
    }
}

__global__ __launch_bounds__(THREADS, 1)
void fused_lin_inorm_kernel(const float* __restrict__ x,
                            const float* __restrict__ y,
                            const float* __restrict__ w,
                            const float* __restrict__ lb,
                            const float* __restrict__ nw,
                            const float* __restrict__ nb,
                            float* __restrict__ out) {
    extern __shared__ float sm[];
    const int tid  = threadIdx.x;
    const int wid  = tid >> 5;
    const int lane = tid & 31;
    const int g    = lane >> 2;
    const int tig  = lane & 3;
    const int m0   = (wid >> 1) * 32;     // 4 m-warps
    const int n0   = (wid & 1) * 64;      // 2 n-warps, 64-wide tiles
    const size_t row0 = (size_t)blockIdx.x * MTILE;

    float* xs  = sm + X_OFF;
    float* wb0 = sm + W0_OFF;
    float* wb1 = sm + W1_OFF;
    const uint32_t sb_u32 = smem_u32(sm);
    const uint32_t w0_u32 = sb_u32 + W0_OFF * 4;
    const uint32_t w1_u32 = sb_u32 + W1_OFF * 4;

    if (tid < 128) sm[SQ_OFF + tid] = 0.0f;

    // Kick off G -> buf0 and w chunk 0 -> buf1 immediately.
    issue_w_chunk(w0_u32, g_G, tid);
    CP_COMMIT();
    issue_w_chunk(w1_u32, w, tid);
    CP_COMMIT();

    load_x_tile(xs, x + row0 * IN, tid);
    __syncthreads();   // x + SQ zeros visible

    // x fragments -> registers (held for all 17 chunks).
    uint32_t areg[2][16][4];
    #pragma unroll
    for (int mt = 0; mt < 2; ++mt) {
        const float* r1 = xs + (m0 + mt * 16 + g) * TS;
        const float* r2 = r1 + 8 * TS;
        #pragma unroll
        for (int s = 0; s < 16; ++s) {
            areg[mt][s][0] = __float_as_uint(r1[s * 8 + tig]);
            areg[mt][s][1] = __float_as_uint(r2[s * 8 + tig]);
            areg[mt][s][2] = __float_as_uint(r1[s * 8 + tig + 4]);
            areg[mt][s][3] = __float_as_uint(r2[s * 8 + tig + 4]);
        }
    }

    // Per-row mean and x'.c (constants are L1/L2 resident).
    if (tid < 128) {
        float dm = 0.0f, dc = 0.0f;
        const float* xr = xs + tid * TS;
        #pragma unroll 8
        for (int k = 0; k < IN; ++k) {
            float xv = xr[k];
            dm += xv * g_sw[k];
            dc += xv * g_c[k];
        }
        sm[MEAN_OFF + tid] = (dm + g_db[1]) * (1.0f / OUT);
        sm[DOTC_OFF + tid] = dc;
    }

    CP_WAIT(1);        // G resident (w0 may still be in flight)
    __syncthreads();

    // ---- stats chunk: Z = x' @ G, rsq = sum Z.*x' per row ----
    {
        float acc[2][8][4];
        compute_chunk_reg(areg, wb0, n0, g, tig, acc);

        float rsq[4] = {0.f, 0.f, 0.f, 0.f};
        #pragma unroll
        for (int mt = 0; mt < 2; ++mt)
            #pragma unroll
            for (int h = 0; h < 2; ++h) {
                const float* xrow = xs + (m0 + mt * 16 + h * 8 + g) * TS;
                #pragma unroll
                for (int nt = 0; nt < 8; ++nt)
                    #pragma unroll
                    for (int p = 0; p < 2; ++p)
                        rsq[mt * 2 + h] += acc[mt][nt][h * 2 + p] *
                                           xrow[n0 + nt * 8 + tig * 2 + p];
            }
        #pragma unroll
        for (int j = 0; j < 4; ++j) {
            rsq[j] += __shfl_xor_sync(0xffffffffu, rsq[j], 1);
            rsq[j] += __shfl_xor_sync(0xffffffffu, rsq[j], 2);
        }
        if (tig == 0) {
            #pragma unroll
            for (int j = 0; j < 4; ++j) {
                int r = m0 + (j >> 1) * 16 + (j & 1) * 8 + g;
                atomicAdd(&sm[SQ_OFF + r], rsq[j]);
            }
        }
    }
    __syncthreads();   // rsq atomics complete; buf0 free

    // Issue w chunk 1 into the freed buf0.
    issue_w_chunk(w0_u32, w + (size_t)NCHUNK * IN, tid);
    CP_COMMIT();

    if (tid < 128) {
        float sumsq = sm[SQ_OFF + tid] + 2.0f * sm[DOTC_OFF + tid] + g_db[0];
        float mean  = sm[MEAN_OFF + tid];
        float var   = sumsq * (1.0f / OUT) - mean * mean;
        sm[ISTD_OFF + tid] = rsqrtf(var + 1e-5f);
    }
    __syncthreads();

    float meanv[4], istdv[4];
    #pragma unroll
    for (int j = 0; j < 4; ++j) {
        int r = m0 + (j >> 1) * 16 + (j & 1) * 8 + g;
        meanv[j] = sm[MEAN_OFF + r];
        istdv[j] = sm[ISTD_OFF + r];
    }

    // ---------------- main loop: chunks 0..15, double-buffered ----------------
    // Pending at top of iter ch: {w_ch, w_{ch+1}} (ch<=14), {w15} at ch=15.
    for (int ch = 0; ch < NCHUNKS; ++ch) {
        if (ch < NCHUNKS - 1) { CP_WAIT(1); } else { CP_WAIT(0); }
        __syncthreads();   // w_ch visible

        const float* wbuf = (ch & 1) ? wb0 : wb1;  // w0->wb1, w1->wb0, alternating
        float acc[2][8][4];
        compute_chunk_reg(areg, wbuf, n0, g, tig, acc);

        const int gcb = ch * NCHUNK + n0 + tig * 2;
        #pragma unroll
        for (int mt = 0; mt < 2; ++mt)
            #pragma unroll
            for (int h = 0; h < 2; ++h) {
                int j = mt * 2 + h;
                size_t grow = row0 + (size_t)(m0 + mt * 16 + h * 8 + g);
                const float* yr  = y   + grow * OUT + gcb;
                float*       orw = out + grow * OUT + gcb;
                #pragma unroll
                for (int nt = 0; nt < 8; ++nt) {
                    float2 lbv = __ldg(reinterpret_cast<const float2*>(lb + gcb + nt * 8));
                    float2 nwv = __ldg(reinterpret_cast<const float2*>(nw + gcb + nt * 8));
                    float2 nbv = __ldg(reinterpret_cast<const float2*>(nb + gcb + nt * 8));
                    float2 yv  = *reinterpret_cast<const float2*>(yr + nt * 8);
                    float v0 = acc[mt][nt][h * 2 + 0] + lbv.x;
                    float v1 = acc[mt][nt][h * 2 + 1] + lbv.y;
                    float nm0 = (v0 - meanv[j]) * istdv[j] * nwv.x + nbv.x;
                    float nm1 = (v1 - meanv[j]) * istdv[j] * nwv.y + nbv.y;
                    float2 ov;
                    ov.x = (nm0 + yv.x) * yv.x;
                    ov.y = (nm1 + yv.y) * yv.y;
                    *reinterpret_cast<float2*>(orw + nt * 8) = ov;
                }
            }
        __syncthreads();   // release wbuf

        if (ch + 2 < NCHUNKS) {
            // refill the buffer just freed with chunk ch+2
            issue_w_chunk((ch & 1) ? w0_u32 : w1_u32,
                          w + (size_t)(ch + 2) * NCHUNK * IN, tid);
            CP_COMMIT();
        }
    }
}

extern "C" void kernel_launch(void* const* d_in, const int* in_sizes, int n_in,
                              void* d_out, int out_size) {
    (void)n_in; (void)out_size;
    const float* x  = (const float*)d_in[0];
    const float* y  = (const float*)d_in[1];
    const float* w  = (const float*)d_in[2];
    const float* lb = (const float*)d_in[3];
    const float* nw = (const float*)d_in[4];
    const float* nb = (const float*)d_in[5];
    float* out = (float*)d_out;

    const int rows = in_sizes[0] / IN;   // 32768
    const int grid = rows / MTILE;       // 256

    static bool configured = false;
    if (!configured) {
        cudaFuncSetAttribute(fused_lin_inorm_kernel,
                             cudaFuncAttributeMaxDynamicSharedMemorySize, SMEM_BYTES);
        configured = true;
    }

    zero_scratch_kernel<<<64, 256>>>();
    gram_kernel<<<OUT / 32, 256>>>(w, lb);
    fused_lin_inorm_kernel<<<grid, THREADS, SMEM_BYTES>>>(x, y, w, lb, nw, nb, out);
}

// round 6
// speedup vs baseline: 1.0647x; 1.0647x over previous
#include <cuda_runtime.h>
#include <cstdint>

// ---------------------------------------------------------------------------
// Fused: h = x @ w^T + b ; instance-norm over OUT ; out = (norm(h)+y)*y
// Single GEMM pass + Gram-identity row stats.
// R6: 512 threads (4m x 4n warps, 32x32 tiles). x and w tiles are stored in a
// fragment-contiguous PERMUTED smem layout so every mma fragment load is one
// LDS.128 (64 per warp per chunk vs 256 LDS.32 before). Per-row skew makes
// all LDS.128 phases bank-conflict-free. w is pre-permuted + tf32-truncated
// into a device buffer by the gram kernel; G / s_w / c written permuted too.
// ---------------------------------------------------------------------------

#define DEVINL __device__ __forceinline__

static constexpr int IN      = 128;
static constexpr int OUT     = 2048;
static constexpr int MTILE   = 128;
static constexpr int NCHUNK  = 128;
static constexpr int NCHUNKS = OUT / NCHUNK;   // 16
static constexpr int THREADS = 512;            // 16 warps: 4m x 4n
static constexpr int TS      = 132;            // smem row stride (floats)

// SMEM layout (floats)
static constexpr int X_OFF    = 0;                  // 128 x 132 (persistent)
static constexpr int W0_OFF   = X_OFF + 128 * TS;
static constexpr int W1_OFF   = W0_OFF + 128 * TS;
static constexpr int MEAN_OFF = W1_OFF + 128 * TS;
static constexpr int DOTC_OFF = MEAN_OFF + 128;
static constexpr int SQ_OFF   = DOTC_OFF + 128;
static constexpr int ISTD_OFF = SQ_OFF + 128;
static constexpr int TOTAL_F  = ISTD_OFF + 128;
static constexpr int SMEM_BYTES = TOTAL_F * 4;      // 204800 B

// ---- device scratch ----
__device__ __align__(16) float g_wp[OUT * IN];   // permuted + truncated w
__device__ __align__(16) float g_G[IN * IN];     // Gram, permuted cols
__device__ __align__(16) float g_c[IN];          // permuted
__device__ __align__(16) float g_sw[IN];         // permuted
__device__ float g_db[2];

DEVINL float tf32_trunc(float f) {
    return __uint_as_float(__float_as_uint(f) & 0xFFFFE000u);
}
DEVINL uint32_t f2tf32(float f) {
    uint32_t r;
    asm("cvt.rna.tf32.f32 %0, %1;" : "=r"(r) : "f"(f));
    return r;
}
DEVINL uint32_t smem_u32(const void* p) {
    uint32_t a;
    asm("{ .reg .u64 t; cvta.to.shared.u64 t, %1; cvt.u32.u64 %0, t; }"
        : "=r"(a) : "l"(p));
    return a;
}
DEVINL void cp_async16(uint32_t saddr, const void* g) {
    asm volatile("cp.async.cg.shared.global [%0], [%1], 16;" :: "r"(saddr), "l"(g));
}
#define CP_COMMIT() asm volatile("cp.async.commit_group;" ::: "memory")
#define CP_WAIT(n)  asm volatile("cp.async.wait_group %0;" :: "n"(n) : "memory")

DEVINL void mma_tf32(float* c, uint32_t a0, uint32_t a1, uint32_t a2, uint32_t a3,
                     uint32_t b0, uint32_t b1) {
    asm volatile(
        "mma.sync.aligned.m16n8k8.row.col.f32.tf32.tf32.f32 "
        "{%0,%1,%2,%3}, {%4,%5,%6,%7}, {%8,%9}, {%0,%1,%2,%3};"
        : "+f"(c[0]), "+f"(c[1]), "+f"(c[2]), "+f"(c[3])
        : "r"(a0), "r"(a1), "r"(a2), "r"(a3), "r"(b0), "r"(b1));
}

// Column permutation: logical k -> packed index within a 128-float row.
// k = 8s + 4h + tig ; i = 2s + h ; sl = (i>>2)*4 + tig ; pidx = sl*4 + (i&3).
DEVINL int permc(int k) {
    int tg = k & 3, h = (k >> 2) & 1, s = k >> 3;
    int i = 2 * s + h;
    return ((i >> 2) * 4 + tg) * 4 + (i & 3);
}
// SMEM float offset of logical (row, k) with per-row segment skew.
DEVINL int xoff_perm(int r, int k) {
    int p = permc(k);
    int sl = p >> 2;
    int seg = (sl + 3 * (r & 1)) & 31;
    return r * TS + seg * 4 + (p & 3);
}

// ---------------- precompute kernels ----------------

__global__ void zero_scratch_kernel() {
    int i = blockIdx.x * blockDim.x + threadIdx.x;
    if (i < IN * IN) g_G[i] = 0.0f;
    if (i < IN) { g_c[i] = 0.0f; g_sw[i] = 0.0f; }
    if (i < 2)  g_db[i] = 0.0f;
}

__global__ __launch_bounds__(256, 1)
void gram_kernel(const float* __restrict__ w, const float* __restrict__ b) {
    __shared__ float ws[32][IN];
    __shared__ float bs[32];
    const int tid   = threadIdx.x;
    const int jbase = blockIdx.x * 32;

    #pragma unroll
    for (int it = 0; it < 4; ++it) {
        int i  = it * 256 + tid;
        int j  = i >> 5;
        int c4 = (i & 31) * 4;
        float4 v = *reinterpret_cast<const float4*>(w + (size_t)(jbase + j) * IN + c4);
        ws[j][c4 + 0] = tf32_trunc(v.x);
        ws[j][c4 + 1] = tf32_trunc(v.y);
        ws[j][c4 + 2] = tf32_trunc(v.z);
        ws[j][c4 + 3] = tf32_trunc(v.w);
    }
    if (tid < 32) bs[tid] = b[jbase + tid];
    __syncthreads();

    // Emit permuted w rows (coalesced 128-float rows).
    #pragma unroll
    for (int it = 0; it < 16; ++it) {
        int i = it * 256 + tid;              // 4096 elements
        int j = i >> 7;
        int q = i & 127;                     // dest packed index
        // invert: q = sl*4+pos ; i2 = (sl>>2)*4+pos ; k = 8*(i2>>1)+4*(i2&1)+ (sl&3)
        int sl = q >> 2, pos = q & 3;
        int i2 = (sl >> 2) * 4 + pos;
        int k  = 8 * (i2 >> 1) + 4 * (i2 & 1) + (sl & 3);
        g_wp[(size_t)(jbase + j) * IN + q] = ws[j][k];
    }

    const int k     = tid & 127;
    const int lbase = (tid >> 7) * 64;
    float acc[64];
    #pragma unroll
    for (int l = 0; l < 64; ++l) acc[l] = 0.0f;
    float ck = 0.0f, swk = 0.0f;

    for (int j = 0; j < 32; ++j) {
        float wk = ws[j][k];
        #pragma unroll
        for (int l = 0; l < 64; ++l) acc[l] += wk * ws[j][lbase + l];
        ck  += bs[j] * wk;
        swk += wk;
    }
    #pragma unroll
    for (int l = 0; l < 64; ++l)
        atomicAdd(&g_G[k * IN + permc(lbase + l)], acc[l]);
    if (tid < IN) {
        atomicAdd(&g_c[permc(k)], ck);
        atomicAdd(&g_sw[permc(k)], swk);
    }
    if (tid < 32) {
        atomicAdd(&g_db[0], bs[tid] * bs[tid]);
        atomicAdd(&g_db[1], bs[tid]);
    }
}

// ---------------- main kernel ----------------

// x tile: global row-major f32 -> permuted tf32 smem (scalar scatter, one-time).
DEVINL void load_x_tile(float* dst, const float* __restrict__ g, int tid) {
    #pragma unroll
    for (int it = 0; it < (128 * 32) / THREADS; ++it) {
        int i  = it * THREADS + tid;
        int r  = i >> 5;
        int c4 = (i & 31) * 4;
        float4 v = *reinterpret_cast<const float4*>(g + (size_t)r * IN + c4);
        int s = c4 >> 3, h = (c4 >> 2) & 1;
        int i2 = 2 * s + h;
        int jj = i2 >> 2, pos = i2 & 3;
        int skew = 3 * (r & 1);
        float vv[4] = {v.x, v.y, v.z, v.w};
        #pragma unroll
        for (int e = 0; e < 4; ++e) {
            int seg = (jj * 4 + e + skew) & 31;
            dst[r * TS + seg * 4 + pos] = __uint_as_float(f2tf32(vv[e]));
        }
    }
}

// w chunk: permuted global rows -> smem with per-row segment skew (16B granules).
DEVINL void issue_w_chunk(uint32_t sbase_b, const float* __restrict__ gsrc, int tid) {
    #pragma unroll
    for (int it = 0; it < (128 * 32) / THREADS; ++it) {
        int gi = it * THREADS + tid;         // granule id
        int r  = gi >> 5;
        int sl = gi & 31;
        int seg = (sl + 3 * (r & 1)) & 31;
        cp_async16(sbase_b + (uint32_t)(r * TS + seg * 4) * 4u,
                   gsrc + (size_t)r * IN + sl * 4);
    }
}

// Warp-tile 32x32 GEMM, K=128, all fragment loads LDS.128 from permuted tiles.
DEVINL void compute_chunk(const float* __restrict__ xs, const float* __restrict__ ws,
                          int m0, int n0, int g, int tig, float acc[2][4][4]) {
    #pragma unroll
    for (int mt = 0; mt < 2; ++mt)
        #pragma unroll
        for (int nt = 0; nt < 4; ++nt)
            #pragma unroll
            for (int q = 0; q < 4; ++q)
                acc[mt][nt][q] = 0.0f;

    const int skew = 3 * (g & 1);   // all touched rows have parity g&1
    #pragma unroll
    for (int j = 0; j < 8; ++j) {
        const int segq = ((j * 4 + tig + skew) & 31) * 4;
        float4 af[2][2], bf[4];
        #pragma unroll
        for (int mt = 0; mt < 2; ++mt) {
            const int r1 = m0 + mt * 16 + g;
            af[mt][0] = *reinterpret_cast<const float4*>(xs + r1 * TS + segq);
            af[mt][1] = *reinterpret_cast<const float4*>(xs + (r1 + 8) * TS + segq);
        }
        #pragma unroll
        for (int nt = 0; nt < 4; ++nt)
            bf[nt] = *reinterpret_cast<const float4*>(ws + (n0 + nt * 8 + g) * TS + segq);

        #pragma unroll
        for (int mt = 0; mt < 2; ++mt)
            #pragma unroll
            for (int nt = 0; nt < 4; ++nt)
                mma_tf32(acc[mt][nt],
                         __float_as_uint(af[mt][0].x), __float_as_uint(af[mt][1].x),
                         __float_as_uint(af[mt][0].y), __float_as_uint(af[mt][1].y),
                         __float_as_uint(bf[nt].x),   __float_as_uint(bf[nt].y));
        #pragma unroll
        for (int mt = 0; mt < 2; ++mt)
            #pragma unroll
            for (int nt = 0; nt < 4; ++nt)
                mma_tf32(acc[mt][nt],
                         __float_as_uint(af[mt][0].z), __float_as_uint(af[mt][1].z),
                         __float_as_uint(af[mt][0].w), __float_as_uint(af[mt][1].w),
                         __float_as_uint(bf[nt].z),   __float_as_uint(bf[nt].w));
    }
}

__global__ __launch_bounds__(THREADS, 1)
void fused_lin_inorm_kernel(const float* __restrict__ x,
                            const float* __restrict__ y,
                            const float* __restrict__ lb,
                            const float* __restrict__ nw,
                            const float* __restrict__ nb,
                            float* __restrict__ out) {
    extern __shared__ float sm[];
    const int tid  = threadIdx.x;
    const int wid  = tid >> 5;
    const int lane = tid & 31;
    const int g    = lane >> 2;
    const int tig  = lane & 3;
    const int m0   = (wid >> 2) * 32;
    const int n0   = (wid & 3) * 32;
    const size_t row0 = (size_t)blockIdx.x * MTILE;

    float* xs  = sm + X_OFF;
    float* wb0 = sm + W0_OFF;
    float* wb1 = sm + W1_OFF;
    const uint32_t sb_u32 = smem_u32(sm);
    const uint32_t w0_u32 = sb_u32 + W0_OFF * 4;
    const uint32_t w1_u32 = sb_u32 + W1_OFF * 4;

    if (tid < 128) sm[SQ_OFF + tid] = 0.0f;

    // G -> buf0, w chunk 0 -> buf1.
    issue_w_chunk(w0_u32, g_G, tid);
    CP_COMMIT();
    issue_w_chunk(w1_u32, g_wp, tid);
    CP_COMMIT();

    load_x_tile(xs, x + row0 * IN, tid);
    __syncthreads();

    // Per-row mean and x'.c (permuted coefficient order, vectorized).
    if (tid < 128) {
        const int r = tid;
        const int skew = 3 * (r & 1);
        float dm = 0.0f, dc = 0.0f;
        #pragma unroll 8
        for (int sl = 0; sl < 32; ++sl) {
            int seg = (sl + skew) & 31;
            float4 xv = *reinterpret_cast<const float4*>(xs + r * TS + seg * 4);
            float4 sv = *reinterpret_cast<const float4*>(g_sw + sl * 4);
            float4 cv = *reinterpret_cast<const float4*>(g_c + sl * 4);
            dm += xv.x * sv.x + xv.y * sv.y + xv.z * sv.z + xv.w * sv.w;
            dc += xv.x * cv.x + xv.y * cv.y + xv.z * cv.z + xv.w * cv.w;
        }
        sm[MEAN_OFF + r] = (dm + g_db[1]) * (1.0f / OUT);
        sm[DOTC_OFF + r] = dc;
    }

    CP_WAIT(1);
    __syncthreads();

    // ---- stats chunk: Z = x' @ G ; rsq = sum Z .* x' per row ----
    {
        float acc[2][4][4];
        compute_chunk(xs, wb0, m0, n0, g, tig, acc);

        float rsq[4] = {0.f, 0.f, 0.f, 0.f};
        #pragma unroll
        for (int mt = 0; mt < 2; ++mt)
            #pragma unroll
            for (int h = 0; h < 2; ++h) {
                const int r = m0 + mt * 16 + h * 8 + g;
                #pragma unroll
                for (int nt = 0; nt < 4; ++nt)
                    #pragma unroll
                    for (int p = 0; p < 2; ++p) {
                        int col = n0 + nt * 8 + tig * 2 + p;
                        rsq[mt * 2 + h] += acc[mt][nt][h * 2 + p] * xs[xoff_perm(r, col)];
                    }
            }
        #pragma unroll
        for (int j = 0; j < 4; ++j) {
            rsq[j] += __shfl_xor_sync(0xffffffffu, rsq[j], 1);
            rsq[j] += __shfl_xor_sync(0xffffffffu, rsq[j], 2);
        }
        if (tig == 0) {
            #pragma unroll
            for (int j = 0; j < 4; ++j) {
                int r = m0 + (j >> 1) * 16 + (j & 1) * 8 + g;
                atomicAdd(&sm[SQ_OFF + r], rsq[j]);
            }
        }
    }
    __syncthreads();   // rsq done; buf0 free

    issue_w_chunk(w0_u32, g_wp + (size_t)NCHUNK * IN, tid);   // chunk 1
    CP_COMMIT();

    if (tid < 128) {
        float sumsq = sm[SQ_OFF + tid] + 2.0f * sm[DOTC_OFF + tid] + g_db[0];
        float mean  = sm[MEAN_OFF + tid];
        float var   = sumsq * (1.0f / OUT) - mean * mean;
        sm[ISTD_OFF + tid] = rsqrtf(var + 1e-5f);
    }
    __syncthreads();

    float meanv[4], istdv[4];
    #pragma unroll
    for (int j = 0; j < 4; ++j) {
        int r = m0 + (j >> 1) * 16 + (j & 1) * 8 + g;
        meanv[j] = sm[MEAN_OFF + r];
        istdv[j] = sm[ISTD_OFF + r];
    }

    // ---------------- main loop: 16 chunks, double-buffered ----------------
    for (int ch = 0; ch < NCHUNKS; ++ch) {
        if (ch < NCHUNKS - 1) { CP_WAIT(1); } else { CP_WAIT(0); }
        __syncthreads();

        const float* wbuf = (ch & 1) ? wb0 : wb1;
        float acc[2][4][4];
        compute_chunk(xs, wbuf, m0, n0, g, tig, acc);

        const int gcb = ch * NCHUNK + n0 + tig * 2;
        #pragma unroll
        for (int mt = 0; mt < 2; ++mt)
            #pragma unroll
            for (int h = 0; h < 2; ++h) {
                int j = mt * 2 + h;
                size_t grow = row0 + (size_t)(m0 + mt * 16 + h * 8 + g);
                const float* yr  = y   + grow * OUT + gcb;
                float*       orw = out + grow * OUT + gcb;
                #pragma unroll
                for (int nt = 0; nt < 4; ++nt) {
                    float2 lbv = __ldg(reinterpret_cast<const float2*>(lb + gcb + nt * 8));
                    float2 nwv = __ldg(reinterpret_cast<const float2*>(nw + gcb + nt * 8));
                    float2 nbv = __ldg(reinterpret_cast<const float2*>(nb + gcb + nt * 8));
                    float2 yv  = *reinterpret_cast<const float2*>(yr + nt * 8);
                    float v0 = acc[mt][nt][h * 2 + 0] + lbv.x;
                    float v1 = acc[mt][nt][h * 2 + 1] + lbv.y;
                    float nm0 = (v0 - meanv[j]) * istdv[j] * nwv.x + nbv.x;
                    float nm1 = (v1 - meanv[j]) * istdv[j] * nwv.y + nbv.y;
                    float2 ov;
                    ov.x = (nm0 + yv.x) * yv.x;
                    ov.y = (nm1 + yv.y) * yv.y;
                    *reinterpret_cast<float2*>(orw + nt * 8) = ov;
                }
            }
        __syncthreads();

        if (ch + 2 < NCHUNKS) {
            issue_w_chunk((ch & 1) ? w0_u32 : w1_u32,
                          g_wp + (size_t)(ch + 2) * NCHUNK * IN, tid);
            CP_COMMIT();
        }
    }
}

extern "C" void kernel_launch(void* const* d_in, const int* in_sizes, int n_in,
                              void* d_out, int out_size) {
    (void)n_in; (void)out_size;
    const float* x  = (const float*)d_in[0];
    const float* y  = (const float*)d_in[1];
    const float* w  = (const float*)d_in[2];
    const float* lb = (const float*)d_in[3];
    const float* nw = (const float*)d_in[4];
    const float* nb = (const float*)d_in[5];
    float* out = (float*)d_out;

    const int rows = in_sizes[0] / IN;   // 32768
    const int grid = rows / MTILE;       // 256

    static bool configured = false;
    if (!configured) {
        cudaFuncSetAttribute(fused_lin_inorm_kernel,
                             cudaFuncAttributeMaxDynamicSharedMemorySize, SMEM_BYTES);
        configured = true;
    }

    zero_scratch_kernel<<<64, 256>>>();
    gram_kernel<<<OUT / 32, 256>>>(w, lb);
    fused_lin_inorm_kernel<<<grid, THREADS, SMEM_BYTES>>>(x, y, lb, nw, nb, out);
}

// round 7
// speedup vs baseline: 1.2210x; 1.1467x over previous
#include <cuda_runtime.h>
#include <cstdint>

// ---------------------------------------------------------------------------
// Fused: h = x @ w^T + b ; instance-norm over OUT ; out = (norm(h)+y)*y
// Single GEMM pass + Gram-identity row stats.
// R7: barrier-free main loop. w is pre-permuted+truncated in gmem (g_wp) and
// read directly via LDG.128 (L1/L2-resident; no smem staging, no cp.async).
// x tile lives in conflict-free permuted smem (read-only after stats), so the
// 16-chunk main loop has ZERO __syncthreads. MTILE=64, 256 thr, 2 CTAs/SM.
// ---------------------------------------------------------------------------

#define DEVINL __device__ __forceinline__

static constexpr int IN      = 128;
static constexpr int OUT     = 2048;
static constexpr int MTILE   = 64;
static constexpr int NCHUNK  = 128;
static constexpr int NCHUNKS = OUT / NCHUNK;   // 16
static constexpr int THREADS = 256;            // 8 warps: 2m x 4n
static constexpr int TS      = 132;            // smem row stride (floats)

// SMEM layout (floats)
static constexpr int X_OFF    = 0;                // 64 x 132
static constexpr int MEAN_OFF = X_OFF + MTILE * TS;
static constexpr int DOTC_OFF = MEAN_OFF + MTILE;
static constexpr int SQ_OFF   = DOTC_OFF + MTILE;
static constexpr int ISTD_OFF = SQ_OFF + MTILE;
static constexpr int TOTAL_F  = ISTD_OFF + MTILE;
static constexpr int SMEM_BYTES = TOTAL_F * 4;    // ~34.8 KB -> 2 CTAs/SM

// ---- device scratch ----
__device__ __align__(16) float g_wp[OUT * IN];   // permuted + tf32-truncated w
__device__ __align__(16) float g_G[IN * IN];     // Gram, permuted cols
__device__ __align__(16) float g_c[IN];          // permuted
__device__ __align__(16) float g_sw[IN];         // permuted
__device__ float g_db[2];

DEVINL float tf32_trunc(float f) {
    return __uint_as_float(__float_as_uint(f) & 0xFFFFE000u);
}
DEVINL uint32_t f2tf32(float f) {
    uint32_t r;
    asm("cvt.rna.tf32.f32 %0, %1;" : "=r"(r) : "f"(f));
    return r;
}

DEVINL void mma_tf32(float* c, uint32_t a0, uint32_t a1, uint32_t a2, uint32_t a3,
                     uint32_t b0, uint32_t b1) {
    asm volatile(
        "mma.sync.aligned.m16n8k8.row.col.f32.tf32.tf32.f32 "
        "{%0,%1,%2,%3}, {%4,%5,%6,%7}, {%8,%9}, {%0,%1,%2,%3};"
        : "+f"(c[0]), "+f"(c[1]), "+f"(c[2]), "+f"(c[3])
        : "r"(a0), "r"(a1), "r"(a2), "r"(a3), "r"(b0), "r"(b1));
}

// Column permutation: logical k -> packed index within a 128-float row.
// k = 8s + 4h + tig ; i = 2s + h ; pidx = ((i>>2)*4 + tig)*4 + (i&3).
// One float4 at slot sl = 4j + tig holds k-steps s = 2j, 2j+1 (both halves).
DEVINL int permc(int k) {
    int tg = k & 3, h = (k >> 2) & 1, s = k >> 3;
    int i = 2 * s + h;
    return ((i >> 2) * 4 + tg) * 4 + (i & 3);
}
// SMEM float offset of logical (row, k) with conflict-free skew slot' = (sl+3r)&31.
DEVINL int xoff_perm(int r, int k) {
    int p = permc(k);
    int sl = p >> 2;
    int seg = (sl + 3 * r) & 31;
    return r * TS + seg * 4 + (p & 3);
}

// ---------------- precompute kernels ----------------

__global__ void zero_scratch_kernel() {
    int i = blockIdx.x * blockDim.x + threadIdx.x;
    if (i < IN * IN) g_G[i] = 0.0f;
    if (i < IN) { g_c[i] = 0.0f; g_sw[i] = 0.0f; }
    if (i < 2)  g_db[i] = 0.0f;
}

__global__ __launch_bounds__(256, 1)
void gram_kernel(const float* __restrict__ w, const float* __restrict__ b) {
    __shared__ float ws[32][IN];
    __shared__ float bs[32];
    const int tid   = threadIdx.x;
    const int jbase = blockIdx.x * 32;

    #pragma unroll
    for (int it = 0; it < 4; ++it) {
        int i  = it * 256 + tid;
        int j  = i >> 5;
        int c4 = (i & 31) * 4;
        float4 v = *reinterpret_cast<const float4*>(w + (size_t)(jbase + j) * IN + c4);
        ws[j][c4 + 0] = tf32_trunc(v.x);
        ws[j][c4 + 1] = tf32_trunc(v.y);
        ws[j][c4 + 2] = tf32_trunc(v.z);
        ws[j][c4 + 3] = tf32_trunc(v.w);
    }
    if (tid < 32) bs[tid] = b[jbase + tid];
    __syncthreads();

    // Emit permuted w rows (coalesced 128-float rows).
    #pragma unroll
    for (int it = 0; it < 16; ++it) {
        int i = it * 256 + tid;              // 4096 elements
        int j = i >> 7;
        int q = i & 127;                     // dest packed index
        int sl = q >> 2, pos = q & 3;
        int i2 = (sl >> 2) * 4 + pos;
        int k  = 8 * (i2 >> 1) + 4 * (i2 & 1) + (sl & 3);
        g_wp[(size_t)(jbase + j) * IN + q] = ws[j][k];
    }

    const int k     = tid & 127;
    const int lbase = (tid >> 7) * 64;
    float acc[64];
    #pragma unroll
    for (int l = 0; l < 64; ++l) acc[l] = 0.0f;
    float ck = 0.0f, swk = 0.0f;

    for (int j = 0; j < 32; ++j) {
        float wk = ws[j][k];
        #pragma unroll
        for (int l = 0; l < 64; ++l) acc[l] += wk * ws[j][lbase + l];
        ck  += bs[j] * wk;
        swk += wk;
    }
    #pragma unroll
    for (int l = 0; l < 64; ++l)
        atomicAdd(&g_G[k * IN + permc(lbase + l)], acc[l]);
    if (tid < IN) {
        atomicAdd(&g_c[permc(k)], ck);
        atomicAdd(&g_sw[permc(k)], swk);
    }
    if (tid < 32) {
        atomicAdd(&g_db[0], bs[tid] * bs[tid]);
        atomicAdd(&g_db[1], bs[tid]);
    }
}

// ---------------- main kernel ----------------

// x tile: global row-major f32 -> permuted tf32 smem (one-time scatter).
DEVINL void load_x_tile(float* dst, const float* __restrict__ g, int tid) {
    #pragma unroll
    for (int it = 0; it < (MTILE * 32) / THREADS; ++it) {
        int i  = it * THREADS + tid;
        int r  = i >> 5;
        int c4 = (i & 31) * 4;
        float4 v = *reinterpret_cast<const float4*>(g + (size_t)r * IN + c4);
        float vv[4] = {v.x, v.y, v.z, v.w};
        #pragma unroll
        for (int e = 0; e < 4; ++e)
            dst[xoff_perm(r, c4 + e)] = __uint_as_float(f2tf32(vv[e]));
    }
}

// Warp-tile 32x32 GEMM, K=128. a: LDS.128 from permuted smem (conflict-free).
// b: LDG.128 from permuted gmem rows (L1/L2 resident), pipelined j -> j+1.
DEVINL void compute_chunk(const float* __restrict__ xs, const float* __restrict__ wg,
                          int m0, int n0, int g, int tig, float acc[2][4][4]) {
    #pragma unroll
    for (int mt = 0; mt < 2; ++mt)
        #pragma unroll
        for (int nt = 0; nt < 4; ++nt)
            #pragma unroll
            for (int q = 0; q < 4; ++q)
                acc[mt][nt][q] = 0.0f;

    float4 bfn[4];
    #pragma unroll
    for (int nt = 0; nt < 4; ++nt)
        bfn[nt] = __ldg(reinterpret_cast<const float4*>(
                        wg + (size_t)(n0 + nt * 8 + g) * IN + tig * 4));

    #pragma unroll
    for (int j = 0; j < 8; ++j) {
        float4 bf[4];
        #pragma unroll
        for (int nt = 0; nt < 4; ++nt) bf[nt] = bfn[nt];
        if (j < 7) {
            #pragma unroll
            for (int nt = 0; nt < 4; ++nt)
                bfn[nt] = __ldg(reinterpret_cast<const float4*>(
                                wg + (size_t)(n0 + nt * 8 + g) * IN + ((j + 1) * 4 + tig) * 4));
        }

        float4 af[2][2];
        #pragma unroll
        for (int mt = 0; mt < 2; ++mt) {
            const int r1 = m0 + mt * 16 + g;
            const int r2 = r1 + 8;
            af[mt][0] = *reinterpret_cast<const float4*>(
                            xs + r1 * TS + (((j * 4 + tig + 3 * r1) & 31) * 4));
            af[mt][1] = *reinterpret_cast<const float4*>(
                            xs + r2 * TS + (((j * 4 + tig + 3 * r2) & 31) * 4));
        }

        #pragma unroll
        for (int mt = 0; mt < 2; ++mt)
            #pragma unroll
            for (int nt = 0; nt < 4; ++nt)
                mma_tf32(acc[mt][nt],
                         __float_as_uint(af[mt][0].x), __float_as_uint(af[mt][1].x),
                         __float_as_uint(af[mt][0].y), __float_as_uint(af[mt][1].y),
                         __float_as_uint(bf[nt].x),   __float_as_uint(bf[nt].y));
        #pragma unroll
        for (int mt = 0; mt < 2; ++mt)
            #pragma unroll
            for (int nt = 0; nt < 4; ++nt)
                mma_tf32(acc[mt][nt],
                         __float_as_uint(af[mt][0].z), __float_as_uint(af[mt][1].z),
                         __float_as_uint(af[mt][0].w), __float_as_uint(af[mt][1].w),
                         __float_as_uint(bf[nt].z),   __float_as_uint(bf[nt].w));
    }
}

__global__ __launch_bounds__(THREADS, 2)
void fused_lin_inorm_kernel(const float* __restrict__ x,
                            const float* __restrict__ y,
                            const float* __restrict__ lb,
                            const float* __restrict__ nw,
                            const float* __restrict__ nb,
                            float* __restrict__ out) {
    __shared__ float sm[TOTAL_F];
    const int tid  = threadIdx.x;
    const int wid  = tid >> 5;
    const int lane = tid & 31;
    const int g    = lane >> 2;
    const int tig  = lane & 3;
    const int m0   = (wid >> 2) * 32;    // 2 m-warp rows
    const int n0   = (wid & 3) * 32;     // 4 n-warp cols
    const size_t row0 = (size_t)blockIdx.x * MTILE;

    float* xs = sm + X_OFF;

    if (tid < MTILE) sm[SQ_OFF + tid] = 0.0f;
    load_x_tile(xs, x + row0 * IN, tid);
    __syncthreads();

    // Per-row mean and x'.c (permuted coefficient order).
    if (tid < MTILE) {
        const int r = tid;
        float dm = 0.0f, dc = 0.0f;
        #pragma unroll 8
        for (int sl = 0; sl < 32; ++sl) {
            int seg = (sl + 3 * r) & 31;
            float4 xv = *reinterpret_cast<const float4*>(xs + r * TS + seg * 4);
            float4 sv = *reinterpret_cast<const float4*>(g_sw + sl * 4);
            float4 cv = *reinterpret_cast<const float4*>(g_c + sl * 4);
            dm += xv.x * sv.x + xv.y * sv.y + xv.z * sv.z + xv.w * sv.w;
            dc += xv.x * cv.x + xv.y * cv.y + xv.z * cv.z + xv.w * cv.w;
        }
        sm[MEAN_OFF + r] = (dm + g_db[1]) * (1.0f / OUT);
        sm[DOTC_OFF + r] = dc;
    }

    // ---- stats chunk: Z = x' @ G ; rsq = sum Z .* x' per row ----
    {
        float acc[2][4][4];
        compute_chunk(xs, g_G, m0, n0, g, tig, acc);

        float rsq[4] = {0.f, 0.f, 0.f, 0.f};
        #pragma unroll
        for (int mt = 0; mt < 2; ++mt)
            #pragma unroll
            for (int h = 0; h < 2; ++h) {
                const int r = m0 + mt * 16 + h * 8 + g;
                #pragma unroll
                for (int nt = 0; nt < 4; ++nt)
                    #pragma unroll
                    for (int p = 0; p < 2; ++p) {
                        int col = n0 + nt * 8 + tig * 2 + p;
                        rsq[mt * 2 + h] += acc[mt][nt][h * 2 + p] * xs[xoff_perm(r, col)];
                    }
            }
        #pragma unroll
        for (int j = 0; j < 4; ++j) {
            rsq[j] += __shfl_xor_sync(0xffffffffu, rsq[j], 1);
            rsq[j] += __shfl_xor_sync(0xffffffffu, rsq[j], 2);
        }
        if (tig == 0) {
            #pragma unroll
            for (int j = 0; j < 4; ++j) {
                int r = m0 + (j >> 1) * 16 + (j & 1) * 8 + g;
                atomicAdd(&sm[SQ_OFF + r], rsq[j]);
            }
        }
    }
    __syncthreads();

    if (tid < MTILE) {
        float sumsq = sm[SQ_OFF + tid] + 2.0f * sm[DOTC_OFF + tid] + g_db[0];
        float mean  = sm[MEAN_OFF + tid];
        float var   = sumsq * (1.0f / OUT) - mean * mean;
        sm[ISTD_OFF + tid] = rsqrtf(var + 1e-5f);
    }
    __syncthreads();

    float meanv[4], istdv[4];
    #pragma unroll
    for (int j = 0; j < 4; ++j) {
        int r = m0 + (j >> 1) * 16 + (j & 1) * 8 + g;
        meanv[j] = sm[MEAN_OFF + r];
        istdv[j] = sm[ISTD_OFF + r];
    }

    // ---------------- main loop: 16 chunks, NO barriers ----------------
    #pragma unroll 1
    for (int ch = 0; ch < NCHUNKS; ++ch) {
        float acc[2][4][4];
        compute_chunk(xs, g_wp + (size_t)ch * NCHUNK * IN, m0, n0, g, tig, acc);

        const int gcb = ch * NCHUNK + n0 + tig * 2;
        #pragma unroll
        for (int mt = 0; mt < 2; ++mt)
            #pragma unroll
            for (int h = 0; h < 2; ++h) {
                int j = mt * 2 + h;
                size_t grow = row0 + (size_t)(m0 + mt * 16 + h * 8 + g);
                const float* yr  = y   + grow * OUT + gcb;
                float*       orw = out + grow * OUT + gcb;
                #pragma unroll
                for (int nt = 0; nt < 4; ++nt) {
                    float2 lbv = __ldg(reinterpret_cast<const float2*>(lb + gcb + nt * 8));
                    float2 nwv = __ldg(reinterpret_cast<const float2*>(nw + gcb + nt * 8));
                    float2 nbv = __ldg(reinterpret_cast<const float2*>(nb + gcb + nt * 8));
                    float2 yv  = *reinterpret_cast<const float2*>(yr + nt * 8);
                    float v0 = acc[mt][nt][h * 2 + 0] + lbv.x;
                    float v1 = acc[mt][nt][h * 2 + 1] + lbv.y;
                    float nm0 = (v0 - meanv[j]) * istdv[j] * nwv.x + nbv.x;
                    float nm1 = (v1 - meanv[j]) * istdv[j] * nwv.y + nbv.y;
                    float2 ov;
                    ov.x = (nm0 + yv.x) * yv.x;
                    ov.y = (nm1 + yv.y) * yv.y;
                    *reinterpret_cast<float2*>(orw + nt * 8) = ov;
                }
            }
    }
}

extern "C" void kernel_launch(void* const* d_in, const int* in_sizes, int n_in,
                              void* d_out, int out_size) {
    (void)n_in; (void)out_size;
    const float* x  = (const float*)d_in[0];
    const float* y  = (const float*)d_in[1];
    const float* w  = (const float*)d_in[2];
    const float* lb = (const float*)d_in[3];
    const float* nw = (const float*)d_in[4];
    const float* nb = (const float*)d_in[5];
    float* out = (float*)d_out;

    const int rows = in_sizes[0] / IN;   // 32768
    const int grid = rows / MTILE;       // 512

    zero_scratch_kernel<<<64, 256>>>();
    gram_kernel<<<OUT / 32, 256>>>(w, lb);
    fused_lin_inorm_kernel<<<grid, THREADS>>>(x, y, lb, nw, nb, out);
}